// round 1
// baseline (speedup 1.0000x reference)
#include <cuda_runtime.h>
#include <cstdint>

#define BB 256
#define NN 256
#define IND 64
#define HID 128
#define NOUT 16
#define NL 3
#define NK 4
#define MM (BB*NN)
#define LN_EPS 1e-5f

// Scratch (no allocation allowed; __device__ globals are the sanctioned path)
__device__ float g_y[(size_t)MM * HID];          // node-linear output per layer
__device__ float g_z[(size_t)NK * MM * HID];     // per-bond pre-transformed features [K][B][N][H]
__device__ float g_msg[(size_t)MM * HID];        // aggregated messages
__device__ float g_x[(size_t)MM * HID];          // layer output

// ---------------- packed fp32x2 helpers (Blackwell FFMA2: 2x fp32 rate) ----------------
__device__ __forceinline__ void ffma2(unsigned long long &c, unsigned long long a,
                                      unsigned long long b) {
    asm("fma.rn.f32x2 %0, %1, %2, %0;" : "+l"(c) : "l"(a), "l"(b));
}
__device__ __forceinline__ unsigned long long pack2(float x) {
    unsigned long long r;
    asm("mov.b64 %0, {%1, %1};" : "=l"(r) : "f"(x));
    return r;
}
__device__ __forceinline__ float2 unpack2(unsigned long long v) {
    float2 f;
    asm("mov.b64 {%0, %1}, %2;" : "=f"(f.x), "=f"(f.y) : "l"(v));
    return f;
}

// ---------------------------------------------------------------------------------------
// NT GEMM: Y[m, h] = sum_d X[m, d] * W[h, d]  (+ bias[h])
// X: [MM x D] row-major, W: [128 x D] row-major (torch layout), Y: [MM x 128]
// grid.x = MM/32 row tiles, grid.y = weight-batch (edge bond type k), block = 256
// ---------------------------------------------------------------------------------------
__global__ void lin_nt_kernel(const float* __restrict__ X, const float* __restrict__ W,
                              const float* __restrict__ bias, float* __restrict__ Y,
                              int D, int wstride, int ystride)
{
    const int kb = blockIdx.y;
    const float* Wp = W + (size_t)kb * wstride;
    float* Yp = Y + (size_t)kb * ystride;
    const int m0 = blockIdx.x * 32;

    __shared__ float Xs[32][33];
    __shared__ float Ws[32][132];   // [d][h], padded for vec4-aligned conflict-free reads

    const int tid  = threadIdx.x;
    const int rowg = tid >> 5;      // 0..7  -> rows rowg*4 .. rowg*4+3
    const int colg = tid & 31;      // 0..31 -> cols colg*4 .. colg*4+3

    unsigned long long acc[4][2] = {};  // 4 rows x 4 cols as 2 packed pairs

    for (int dt = 0; dt < D; dt += 32) {
        #pragma unroll
        for (int idx = tid; idx < 32*32; idx += 256) {
            Xs[idx >> 5][idx & 31] = X[(size_t)(m0 + (idx >> 5)) * D + dt + (idx & 31)];
        }
        #pragma unroll
        for (int idx = tid; idx < 128*32; idx += 256) {
            const int h = idx >> 5, c = idx & 31;
            Ws[c][h] = Wp[(size_t)h * D + dt + c];
        }
        __syncthreads();

        #pragma unroll
        for (int c = 0; c < 32; c++) {
            const ulonglong2 bv = *(const ulonglong2*)&Ws[c][colg * 4];
            #pragma unroll
            for (int i = 0; i < 4; i++) {
                const unsigned long long a = pack2(Xs[rowg*4 + i][c]);
                ffma2(acc[i][0], a, bv.x);
                ffma2(acc[i][1], a, bv.y);
            }
        }
        __syncthreads();
    }

    #pragma unroll
    for (int i = 0; i < 4; i++) {
        const float2 v0 = unpack2(acc[i][0]);
        const float2 v1 = unpack2(acc[i][1]);
        float4 o = make_float4(v0.x, v0.y, v1.x, v1.y);
        if (bias) {
            const float4 bq = *(const float4*)&bias[colg * 4];
            o.x += bq.x; o.y += bq.y; o.z += bq.z; o.w += bq.w;
        }
        *(float4*)&Yp[(size_t)(m0 + rowg*4 + i) * HID + colg * 4] = o;
    }
}

// ---------------------------------------------------------------------------------------
// Aggregation: msg[b, n, o] = sum_k sum_m adj[b, k, n, m] * z[k, b, m, o]
// Per block: one b, 64-row tile, full 128 cols. block = 256 threads (16x16 groups),
// 4x8 outputs/thread, accumulated over K and the 256-deep m dimension.
// ---------------------------------------------------------------------------------------
__global__ void aggregate_kernel(const float* __restrict__ adj, const float* __restrict__ z,
                                 float* __restrict__ msg)
{
    const int b = blockIdx.y;
    const int row0 = blockIdx.x * 64;

    __shared__ float As[64][33];
    __shared__ float Zs[32][132];

    const int tid  = threadIdx.x;
    const int rowg = tid >> 4;      // 0..15 -> rows rowg*4 .. +3
    const int colg = tid & 15;      // 0..15 -> cols colg*8 .. +7

    unsigned long long acc[4][4] = {};  // 4 rows x 8 cols as 4 packed pairs

    for (int k = 0; k < NK; k++) {
        const float* Ap = adj + ((size_t)(b * NK + k) * NN + row0) * NN;
        const float* Zp = z   + ((size_t)k * BB + b) * NN * HID;
        for (int m0 = 0; m0 < NN; m0 += 32) {
            #pragma unroll
            for (int idx = tid; idx < 64*32; idx += 256) {
                As[idx >> 5][idx & 31] = Ap[(size_t)(idx >> 5) * NN + m0 + (idx & 31)];
            }
            #pragma unroll
            for (int i4 = tid * 4; i4 < 32*128; i4 += 1024) {
                const int mm = i4 >> 7, h = i4 & 127;
                *(float4*)&Zs[mm][h] = *(const float4*)&Zp[(size_t)(m0 + mm) * HID + h];
            }
            __syncthreads();

            #pragma unroll
            for (int mm = 0; mm < 32; mm++) {
                const ulonglong2 bv0 = *(const ulonglong2*)&Zs[mm][colg * 8];
                const ulonglong2 bv1 = *(const ulonglong2*)&Zs[mm][colg * 8 + 4];
                #pragma unroll
                for (int i = 0; i < 4; i++) {
                    const unsigned long long a = pack2(As[rowg*4 + i][mm]);
                    ffma2(acc[i][0], a, bv0.x);
                    ffma2(acc[i][1], a, bv0.y);
                    ffma2(acc[i][2], a, bv1.x);
                    ffma2(acc[i][3], a, bv1.y);
                }
            }
            __syncthreads();
        }
    }

    #pragma unroll
    for (int i = 0; i < 4; i++) {
        const int r = row0 + rowg*4 + i;
        const float2 v0 = unpack2(acc[i][0]), v1 = unpack2(acc[i][1]);
        const float2 v2 = unpack2(acc[i][2]), v3 = unpack2(acc[i][3]);
        const float4 o0 = make_float4(v0.x, v0.y, v1.x, v1.y);
        const float4 o1 = make_float4(v2.x, v2.y, v3.x, v3.y);
        *(float4*)&msg[((size_t)b * NN + r) * HID + colg * 8]     = o0;
        *(float4*)&msg[((size_t)b * NN + r) * HID + colg * 8 + 4] = o1;
    }
}

// ---------------------------------------------------------------------------------------
// Fused: v = y + msg + sum_k edge_b[k];  x = relu(LayerNorm(v) * g + b)
// One 128-thread block per row.
// ---------------------------------------------------------------------------------------
__global__ void ln_relu_kernel(const float* __restrict__ y, const float* __restrict__ msgp,
                               const float* __restrict__ eb, const float* __restrict__ g,
                               const float* __restrict__ bt, float* __restrict__ xout)
{
    const int m = blockIdx.x;
    const int h = threadIdx.x;
    const size_t o = (size_t)m * HID + h;
    float v = y[o] + msgp[o] + eb[h] + eb[HID + h] + eb[2*HID + h] + eb[3*HID + h];

    float s = v, s2 = v * v;
    #pragma unroll
    for (int d = 16; d > 0; d >>= 1) {
        s  += __shfl_xor_sync(0xffffffffu, s,  d);
        s2 += __shfl_xor_sync(0xffffffffu, s2, d);
    }
    __shared__ float red[8];
    if ((h & 31) == 0) { red[h >> 5] = s; red[4 + (h >> 5)] = s2; }
    __syncthreads();
    s  = red[0] + red[1] + red[2] + red[3];
    s2 = red[4] + red[5] + red[6] + red[7];

    const float mu  = s * (1.0f / HID);
    const float var = s2 * (1.0f / HID) - mu * mu;
    const float r   = rsqrtf(var + LN_EPS);
    const float out = (v - mu) * r * g[h] + bt[h];
    xout[o] = fmaxf(out, 0.0f);
}

// ---------------------------------------------------------------------------------------
// Readout: out[b, :] = (sum_n x[b, n, :]) @ out_W^T + out_b
// ---------------------------------------------------------------------------------------
__global__ void readout_kernel(const float* __restrict__ x, const float* __restrict__ oW,
                               const float* __restrict__ ob, float* __restrict__ out)
{
    const int b = blockIdx.x;
    const int h = threadIdx.x;
    float s = 0.0f;
    const float* xp = x + (size_t)b * NN * HID + h;
    #pragma unroll 8
    for (int n = 0; n < NN; n++) s += xp[(size_t)n * HID];
    __shared__ float repr[HID];
    repr[h] = s;
    __syncthreads();
    if (h < NOUT) {
        float acc = ob[h];
        #pragma unroll 8
        for (int d = 0; d < HID; d++) acc += repr[d] * oW[h * HID + d];
        out[b * NOUT + h] = acc;
    }
}

// ---------------------------------------------------------------------------------------
extern "C" void kernel_launch(void* const* d_in, const int* in_sizes, int n_in,
                              void* d_out, int out_size)
{
    const float* feat = (const float*)d_in[0];
    const float* adj  = (const float*)d_in[1];
    const float* nW[3] = {(const float*)d_in[2], (const float*)d_in[4], (const float*)d_in[6]};
    const float* nb[3] = {(const float*)d_in[3], (const float*)d_in[5], (const float*)d_in[7]};
    const float* eW  = (const float*)d_in[8];
    const float* ebp = (const float*)d_in[9];
    const float* lng = (const float*)d_in[10];
    const float* lnb = (const float*)d_in[11];
    const float* oW  = (const float*)d_in[12];
    const float* ob  = (const float*)d_in[13];

    float *y, *z, *msgp, *xb;
    cudaGetSymbolAddress((void**)&y,    g_y);
    cudaGetSymbolAddress((void**)&z,    g_z);
    cudaGetSymbolAddress((void**)&msgp, g_msg);
    cudaGetSymbolAddress((void**)&xb,   g_x);

    const float* xin = feat;
    int D = IND;
    for (int l = 0; l < NL; l++) {
        // y = xin @ node_W[l]^T + node_b[l]
        lin_nt_kernel<<<dim3(MM/32, 1), 256>>>(xin, nW[l], nb[l], y, D, 0, 0);
        // z[k] = y @ edge_W[k]^T   (bias folded into LN stage as edge_b sum)
        lin_nt_kernel<<<dim3(MM/32, NK), 256>>>(y, eW, nullptr, z, HID, HID*HID, MM*HID);
        // msg = sum_k adj[:,k] @ z[k]
        aggregate_kernel<<<dim3(NN/64, BB), 256>>>(adj, z, msgp);
        // x = relu(LN(y + msg + sum_k edge_b[k]))
        ln_relu_kernel<<<MM, HID>>>(y, msgp, ebp, lng + l*HID, lnb + l*HID, xb);
        xin = xb; D = HID;
    }
    readout_kernel<<<BB, HID>>>(xb, oW, ob, (float*)d_out);
}

// round 3
// speedup vs baseline: 3.2425x; 3.2425x over previous
#include <cuda_runtime.h>
#include <cuda_bf16.h>
#include <cstdint>

#define BB 256
#define NN 256
#define IND 64
#define HID 128
#define NOUT 16
#define NL 3
#define NK 4
#define MM (BB*NN)
#define LN_EPS 1e-5f
#define EP 136                       // smem pitch in u16 (272B), ldmatrix conflict-free

// ------------------------------- scratch (device globals; no allocs) -------------------
__device__ float    g_y[(size_t)MM * HID];          // node-linear output fp32 (residual)
__device__ uint16_t g_yhi[(size_t)MM * HID];        // y split hi plane (bf16 bits)
__device__ uint16_t g_ylo[(size_t)MM * HID];        // y split lo plane
__device__ float    g_msg[(size_t)MM * HID];
__device__ float    g_x[(size_t)MM * HID];
__device__ uint16_t g_wThi[(size_t)NK * HID * HID]; // edge W transposed [k][d][h], hi
__device__ uint16_t g_wTlo[(size_t)NK * HID * HID];

// ------------------------------- helpers -------------------------------
__device__ __forceinline__ void splitf(float a, uint16_t &h, uint16_t &l) {
    __nv_bfloat16 bh = __float2bfloat16(a);
    float res = a - __bfloat162float(bh);
    __nv_bfloat16 bl = __float2bfloat16(res);
    h = __bfloat16_as_ushort(bh);
    l = __bfloat16_as_ushort(bl);
}
__device__ __forceinline__ uint32_t packu(uint16_t a, uint16_t b) {
    return (uint32_t)a | ((uint32_t)b << 16);
}
__device__ __forceinline__ uint32_t cvta_s(const void* p) {
    return (uint32_t)__cvta_generic_to_shared(p);
}
__device__ __forceinline__ void ldsm_x4_t(uint32_t* r, uint32_t addr) {
    asm volatile("ldmatrix.sync.aligned.m8n8.x4.trans.shared.b16 {%0,%1,%2,%3}, [%4];"
                 : "=r"(r[0]), "=r"(r[1]), "=r"(r[2]), "=r"(r[3]) : "r"(addr));
}
__device__ __forceinline__ void mma_bf16(float* c, const uint32_t* a, const uint32_t* b) {
    asm volatile("mma.sync.aligned.m16n8k16.row.col.f32.bf16.bf16.f32 "
                 "{%0,%1,%2,%3}, {%4,%5,%6,%7}, {%8,%9}, {%0,%1,%2,%3};"
                 : "+f"(c[0]), "+f"(c[1]), "+f"(c[2]), "+f"(c[3])
                 : "r"(a[0]), "r"(a[1]), "r"(a[2]), "r"(a[3]), "r"(b[0]), "r"(b[1]));
}
__device__ __forceinline__ void cp16(uint32_t dst, const void* src) {
    asm volatile("cp.async.cg.shared.global [%0], [%1], 16;" :: "r"(dst), "l"(src));
}
#define CP_COMMIT() asm volatile("cp.async.commit_group;")
#define CP_WAIT(n)  asm volatile("cp.async.wait_group %0;" :: "n"(n))

// packed fp32x2 for node GEMM
__device__ __forceinline__ void ffma2(unsigned long long &c, unsigned long long a,
                                      unsigned long long b) {
    asm("fma.rn.f32x2 %0, %1, %2, %0;" : "+l"(c) : "l"(a), "l"(b));
}
__device__ __forceinline__ unsigned long long pack2(float x) {
    unsigned long long r;
    asm("mov.b64 %0, {%1, %1};" : "=l"(r) : "f"(x));
    return r;
}
__device__ __forceinline__ float2 unpack2(unsigned long long v) {
    float2 f;
    asm("mov.b64 {%0, %1}, %2;" : "=f"(f.x), "=f"(f.y) : "l"(v));
    return f;
}

// ---------------------------------------------------------------------------------------
// Node linear (FFMA2): Y[m,h] = sum_d X[m,d]*W[h,d] + b[h]; also emits split bf16 planes.
// ---------------------------------------------------------------------------------------
__global__ void lin_nt_kernel(const float* __restrict__ X, const float* __restrict__ W,
                              const float* __restrict__ bias, float* __restrict__ Y,
                              uint16_t* __restrict__ Yhi, uint16_t* __restrict__ Ylo, int D)
{
    const int m0 = blockIdx.x * 32;
    __shared__ float Xs[32][33];
    __shared__ float Ws[32][132];
    const int tid = threadIdx.x;
    const int rowg = tid >> 5;
    const int colg = tid & 31;
    unsigned long long acc[4][2] = {};

    for (int dt = 0; dt < D; dt += 32) {
        #pragma unroll
        for (int idx = tid; idx < 32*32; idx += 256)
            Xs[idx >> 5][idx & 31] = X[(size_t)(m0 + (idx >> 5)) * D + dt + (idx & 31)];
        #pragma unroll
        for (int idx = tid; idx < 128*32; idx += 256) {
            const int h = idx >> 5, c = idx & 31;
            Ws[c][h] = W[(size_t)h * D + dt + c];
        }
        __syncthreads();
        #pragma unroll
        for (int c = 0; c < 32; c++) {
            const ulonglong2 bv = *(const ulonglong2*)&Ws[c][colg * 4];
            #pragma unroll
            for (int i = 0; i < 4; i++) {
                const unsigned long long a = pack2(Xs[rowg*4 + i][c]);
                ffma2(acc[i][0], a, bv.x);
                ffma2(acc[i][1], a, bv.y);
            }
        }
        __syncthreads();
    }
    #pragma unroll
    for (int i = 0; i < 4; i++) {
        const float2 v0 = unpack2(acc[i][0]);
        const float2 v1 = unpack2(acc[i][1]);
        const float4 bq = *(const float4*)&bias[colg * 4];
        float4 o = make_float4(v0.x + bq.x, v0.y + bq.y, v1.x + bq.z, v1.y + bq.w);
        const size_t off = (size_t)(m0 + rowg*4 + i) * HID + colg * 4;
        *(float4*)&Y[off] = o;
        uint16_t h0,h1,h2,h3,l0,l1,l2,l3;
        splitf(o.x,h0,l0); splitf(o.y,h1,l1); splitf(o.z,h2,l2); splitf(o.w,h3,l3);
        uint32_t* ph = (uint32_t*)&Yhi[off];
        uint32_t* pl = (uint32_t*)&Ylo[off];
        ph[0] = packu(h0,h1); ph[1] = packu(h2,h3);
        pl[0] = packu(l0,l1); pl[1] = packu(l2,l3);
    }
}

// ---------------------------------------------------------------------------------------
// Weight prep: eW[k][o][d] -> transposed split planes wT[k][d][o] (hi/lo bf16)
// ---------------------------------------------------------------------------------------
__global__ void prep_edge_w(const float* __restrict__ eW, uint16_t* __restrict__ wThi,
                            uint16_t* __restrict__ wTlo)
{
    int idx = blockIdx.x * 256 + threadIdx.x;   // NK*HID*HID = 65536
    int k = idx >> 14, rem = idx & 16383, o = rem >> 7, d = rem & 127;
    uint16_t hi, lo;
    splitf(eW[idx], hi, lo);
    wThi[(k << 14) + d * HID + o] = hi;
    wTlo[(k << 14) + d * HID + o] = lo;
}

// ---------------------------------------------------------------------------------------
// Fused message passing: msg[b,n,o] = sum_k sum_d ( sum_m adj[b,k,n,m] * y[b,m,d] ) * W[k,o,d]
// Grid (2, BB): block = 128 n-rows of one b; 8 warps, each warp 16 rows x 128 cols.
// GEMM1: neigh_k (regs) += adj-chunk (direct LDG frags, split) @ y-chunk (smem, split)
// GEMM2: msg += neigh_k (C-frags reinterpreted as A-frags, split) @ Wk^T (smem, split)
// ---------------------------------------------------------------------------------------
__global__ __launch_bounds__(256, 1) void fused_mp(
    const float* __restrict__ adj, const uint16_t* __restrict__ yhi,
    const uint16_t* __restrict__ ylo, const uint16_t* __restrict__ wThi,
    const uint16_t* __restrict__ wTlo, float* __restrict__ msg)
{
    __shared__ __align__(16) uint16_t sB[2][2][16][EP];   // [buf][plane][row16][col]

    const int b = blockIdx.y;
    const int n0 = blockIdx.x * 128;
    const int tid = threadIdx.x, warp = tid >> 5, lane = tid & 31;
    const int wrow = n0 + warp * 16;           // this warp's global n-row base
    const int rB = tid >> 4, oB = tid & 15;    // staging coords (16 rows x 16 16B-chunks)
    const int ar = lane >> 2, ac = (lane & 3) * 2;

    const uint32_t sb0  = cvta_s(&sB[0][0][0][0]);
    const uint32_t BUFB = 2 * 16 * EP * 2;     // bytes per buffer (both planes)
    const uint32_t PLNB = 16 * EP * 2;         // bytes per plane
    const uint32_t rowoff = rB * (EP*2) + oB * 16;
    const uint32_t lds_off = (lane & 15) * (EP*2) + ((lane >> 4) << 4);

    float macc[16][4];
    float nacc[16][4];
    #pragma unroll
    for (int j = 0; j < 16; j++)
        #pragma unroll
        for (int t = 0; t < 4; t++) macc[j][t] = 0.f;

    float2 adjA[4], adjB[4];

#define ADJ_LOAD(K_, MC_, DST) do {                                                      \
    const float* Ap_ = adj + (((size_t)((b)*NK + (K_)) * NN + wrow) * NN) + (MC_)*16;    \
    DST[0] = *(const float2*)(Ap_ + (size_t)ar*NN + ac);                                 \
    DST[1] = *(const float2*)(Ap_ + (size_t)(ar+8)*NN + ac);                             \
    DST[2] = *(const float2*)(Ap_ + (size_t)ar*NN + ac + 8);                             \
    DST[3] = *(const float2*)(Ap_ + (size_t)(ar+8)*NN + ac + 8);                         \
} while(0)

#define PRE_Y(MC_, BUF_) do {                                                            \
    size_t o_ = ((size_t)b*NN + (MC_)*16 + rB) * HID + oB*8;                             \
    cp16(sb0 + (BUF_)*BUFB + rowoff, yhi + o_);                                          \
    cp16(sb0 + (BUF_)*BUFB + PLNB + rowoff, ylo + o_);                                   \
} while(0)

#define PRE_W(K_, HC_, BUF_) do {                                                        \
    size_t o_ = ((size_t)(K_) << 14) + ((HC_)*16 + rB) * 128 + oB*8;                     \
    cp16(sb0 + (BUF_)*BUFB + rowoff, wThi + o_);                                         \
    cp16(sb0 + (BUF_)*BUFB + PLNB + rowoff, wTlo + o_);                                  \
} while(0)

#define COMPUTE_Y(BUF_, SRC) do {                                                        \
    uint32_t ah[4], al[4];                                                               \
    _Pragma("unroll")                                                                    \
    for (int q = 0; q < 4; q++) {                                                        \
        uint16_t h0,l0,h1,l1;                                                            \
        splitf(SRC[q].x, h0, l0); splitf(SRC[q].y, h1, l1);                              \
        ah[q] = packu(h0,h1); al[q] = packu(l0,l1);                                      \
    }                                                                                    \
    const uint32_t bh_base = sb0 + (BUF_)*BUFB + lds_off;                                \
    _Pragma("unroll")                                                                    \
    for (int jj = 0; jj < 8; jj++) {                                                     \
        uint32_t bh[4], bl[4];                                                           \
        ldsm_x4_t(bh, bh_base + jj*32);                                                  \
        ldsm_x4_t(bl, bh_base + PLNB + jj*32);                                           \
        _Pragma("unroll")                                                                \
        for (int tp = 0; tp < 2; tp++) {                                                 \
            mma_bf16(nacc[2*jj+tp], ah, &bh[2*tp]);                                      \
            mma_bf16(nacc[2*jj+tp], ah, &bl[2*tp]);                                      \
            mma_bf16(nacc[2*jj+tp], al, &bh[2*tp]);                                      \
        }                                                                                \
    }                                                                                    \
} while(0)

#define COMPUTE_W(BUF_, HC_) do {                                                        \
    uint32_t ah[4], al[4];                                                               \
    {                                                                                    \
        uint16_t h0,l0,h1,l1;                                                            \
        splitf(nacc[2*(HC_)][0],h0,l0);   splitf(nacc[2*(HC_)][1],h1,l1);                \
        ah[0]=packu(h0,h1); al[0]=packu(l0,l1);                                          \
        splitf(nacc[2*(HC_)][2],h0,l0);   splitf(nacc[2*(HC_)][3],h1,l1);                \
        ah[1]=packu(h0,h1); al[1]=packu(l0,l1);                                          \
        splitf(nacc[2*(HC_)+1][0],h0,l0); splitf(nacc[2*(HC_)+1][1],h1,l1);              \
        ah[2]=packu(h0,h1); al[2]=packu(l0,l1);                                          \
        splitf(nacc[2*(HC_)+1][2],h0,l0); splitf(nacc[2*(HC_)+1][3],h1,l1);              \
        ah[3]=packu(h0,h1); al[3]=packu(l0,l1);                                          \
    }                                                                                    \
    const uint32_t bh_base = sb0 + (BUF_)*BUFB + lds_off;                                \
    _Pragma("unroll")                                                                    \
    for (int jj = 0; jj < 8; jj++) {                                                     \
        uint32_t bh[4], bl[4];                                                           \
        ldsm_x4_t(bh, bh_base + jj*32);                                                  \
        ldsm_x4_t(bl, bh_base + PLNB + jj*32);                                           \
        _Pragma("unroll")                                                                \
        for (int tp = 0; tp < 2; tp++) {                                                 \
            mma_bf16(macc[2*jj+tp], ah, &bh[2*tp]);                                      \
            mma_bf16(macc[2*jj+tp], ah, &bl[2*tp]);                                      \
            mma_bf16(macc[2*jj+tp], al, &bh[2*tp]);                                      \
        }                                                                                \
    }                                                                                    \
} while(0)

    // ---- pipeline preamble: stage (k=0, mc=0) ----
    ADJ_LOAD(0, 0, adjA);
    PRE_Y(0, 0);
    CP_COMMIT();

    for (int k = 0; k < NK; ++k) {
        #pragma unroll
        for (int j = 0; j < 16; j++)
            #pragma unroll
            for (int t = 0; t < 4; t++) nacc[j][t] = 0.f;

        for (int mc2 = 0; mc2 < 8; ++mc2) {
            PRE_Y(2*mc2 + 1, 1);
            ADJ_LOAD(k, 2*mc2 + 1, adjB);
            CP_COMMIT(); CP_WAIT(1); __syncthreads();
            COMPUTE_Y(0, adjA);
            __syncthreads();

            if (mc2 < 7) { PRE_Y(2*mc2 + 2, 0); ADJ_LOAD(k, 2*mc2 + 2, adjA); }
            else         { PRE_W(k, 0, 0); }
            CP_COMMIT(); CP_WAIT(1); __syncthreads();
            COMPUTE_Y(1, adjB);
            __syncthreads();
        }

        #pragma unroll
        for (int hc2 = 0; hc2 < 4; ++hc2) {
            PRE_W(k, 2*hc2 + 1, 1);
            CP_COMMIT(); CP_WAIT(1); __syncthreads();
            COMPUTE_W(0, 2*hc2);
            __syncthreads();

            if (hc2 < 3)      { PRE_W(k, 2*hc2 + 2, 0); }
            else if (k < NK-1){ PRE_Y(0, 0); ADJ_LOAD(k+1, 0, adjA); }
            CP_COMMIT(); CP_WAIT(1); __syncthreads();
            COMPUTE_W(1, 2*hc2 + 1);
            __syncthreads();
        }
    }

    // epilogue: write msg (fp32), C-fragment layout
    const int row = wrow + (lane >> 2);
    #pragma unroll
    for (int j = 0; j < 16; j++) {
        const int col = j*8 + (lane & 3)*2;
        float* o = msg + ((size_t)b * NN + row) * HID + col;
        o[0] = macc[j][0]; o[1] = macc[j][1];
        float* o2 = o + 8 * HID;
        o2[0] = macc[j][2]; o2[1] = macc[j][3];
    }
#undef ADJ_LOAD
#undef PRE_Y
#undef PRE_W
#undef COMPUTE_Y
#undef COMPUTE_W
}

// ---------------------------------------------------------------------------------------
// Fused residual + edge-bias + LayerNorm + ReLU. Warp per row, float4 per lane.
// ---------------------------------------------------------------------------------------
__global__ void ln_relu_kernel(const float* __restrict__ y, const float* __restrict__ msgp,
                               const float* __restrict__ eb, const float* __restrict__ g,
                               const float* __restrict__ bt, float* __restrict__ xout)
{
    const int m = blockIdx.x * 4 + (threadIdx.x >> 5);
    const int lane = threadIdx.x & 31;
    const size_t o = (size_t)m * HID + lane * 4;
    const float4 a = *(const float4*)&y[o];
    const float4 c = *(const float4*)&msgp[o];
    const float4 e0 = *(const float4*)&eb[lane*4];
    const float4 e1 = *(const float4*)&eb[HID + lane*4];
    const float4 e2 = *(const float4*)&eb[2*HID + lane*4];
    const float4 e3 = *(const float4*)&eb[3*HID + lane*4];
    float4 v;
    v.x = a.x + c.x + e0.x + e1.x + e2.x + e3.x;
    v.y = a.y + c.y + e0.y + e1.y + e2.y + e3.y;
    v.z = a.z + c.z + e0.z + e1.z + e2.z + e3.z;
    v.w = a.w + c.w + e0.w + e1.w + e2.w + e3.w;

    float s  = v.x + v.y + v.z + v.w;
    float s2 = v.x*v.x + v.y*v.y + v.z*v.z + v.w*v.w;
    #pragma unroll
    for (int d = 16; d > 0; d >>= 1) {
        s  += __shfl_xor_sync(0xffffffffu, s,  d);
        s2 += __shfl_xor_sync(0xffffffffu, s2, d);
    }
    const float mu  = s * (1.0f / HID);
    const float var = s2 * (1.0f / HID) - mu * mu;
    const float r   = rsqrtf(var + LN_EPS);
    const float4 gg = *(const float4*)&g[lane*4];
    const float4 bb = *(const float4*)&bt[lane*4];
    float4 out;
    out.x = fmaxf((v.x - mu) * r * gg.x + bb.x, 0.f);
    out.y = fmaxf((v.y - mu) * r * gg.y + bb.y, 0.f);
    out.z = fmaxf((v.z - mu) * r * gg.z + bb.z, 0.f);
    out.w = fmaxf((v.w - mu) * r * gg.w + bb.w, 0.f);
    *(float4*)&xout[o] = out;
}

// ---------------------------------------------------------------------------------------
__global__ void readout_kernel(const float* __restrict__ x, const float* __restrict__ oW,
                               const float* __restrict__ ob, float* __restrict__ out)
{
    const int b = blockIdx.x;
    const int h = threadIdx.x;
    float s = 0.0f;
    const float* xp = x + (size_t)b * NN * HID + h;
    #pragma unroll 8
    for (int n = 0; n < NN; n++) s += xp[(size_t)n * HID];
    __shared__ float repr[HID];
    repr[h] = s;
    __syncthreads();
    if (h < NOUT) {
        float acc = ob[h];
        #pragma unroll 8
        for (int d = 0; d < HID; d++) acc += repr[d] * oW[h * HID + d];
        out[b * NOUT + h] = acc;
    }
}

// ---------------------------------------------------------------------------------------
extern "C" void kernel_launch(void* const* d_in, const int* in_sizes, int n_in,
                              void* d_out, int out_size)
{
    const float* feat = (const float*)d_in[0];
    const float* adj  = (const float*)d_in[1];
    const float* nW[3] = {(const float*)d_in[2], (const float*)d_in[4], (const float*)d_in[6]};
    const float* nb[3] = {(const float*)d_in[3], (const float*)d_in[5], (const float*)d_in[7]};
    const float* eW  = (const float*)d_in[8];
    const float* ebp = (const float*)d_in[9];
    const float* lng = (const float*)d_in[10];
    const float* lnb = (const float*)d_in[11];
    const float* oW  = (const float*)d_in[12];
    const float* ob  = (const float*)d_in[13];

    float *y, *msgp, *xb;
    uint16_t *yhi, *ylo, *wThi, *wTlo;
    cudaGetSymbolAddress((void**)&y,    g_y);
    cudaGetSymbolAddress((void**)&yhi,  g_yhi);
    cudaGetSymbolAddress((void**)&ylo,  g_ylo);
    cudaGetSymbolAddress((void**)&msgp, g_msg);
    cudaGetSymbolAddress((void**)&xb,   g_x);
    cudaGetSymbolAddress((void**)&wThi, g_wThi);
    cudaGetSymbolAddress((void**)&wTlo, g_wTlo);

    prep_edge_w<<<NK * HID * HID / 256, 256>>>(eW, wThi, wTlo);

    const float* xin = feat;
    int D = IND;
    for (int l = 0; l < NL; l++) {
        lin_nt_kernel<<<MM/32, 256>>>(xin, nW[l], nb[l], y, yhi, ylo, D);
        fused_mp<<<dim3(2, BB), 256>>>(adj, yhi, ylo, wThi, wTlo, msgp);
        ln_relu_kernel<<<MM/4, 128>>>(y, msgp, ebp, lng + l*HID, lnb + l*HID, xb);
        xin = xb; D = HID;
    }
    readout_kernel<<<BB, HID>>>(xb, oW, ob, (float*)d_out);
}

// round 4
// speedup vs baseline: 4.0756x; 1.2569x over previous
#include <cuda_runtime.h>
#include <cuda_bf16.h>
#include <cstdint>

#define BB 256
#define NN 256
#define IND 64
#define HID 128
#define NOUT 16
#define NL 3
#define NK 4
#define MM (BB*NN)
#define LN_EPS 1e-5f
#define EP 136                    // smem row pitch in u16 (272B) -> ldmatrix conflict-free
#define EPB (EP*2)                // pitch in bytes

// ------------------------------- scratch (device globals; no allocs) -------------------
__device__ float    g_y[(size_t)MM * HID];          // node-linear output fp32 (residual)
__device__ uint16_t g_yhi[(size_t)MM * HID];
__device__ uint16_t g_ylo[(size_t)MM * HID];
__device__ float    g_x[(size_t)MM * HID];          // layer output fp32
__device__ uint16_t g_xhi[(size_t)MM * HID];        // layer-input split planes (reused)
__device__ uint16_t g_xlo[(size_t)MM * HID];
__device__ uint16_t g_ewh[(size_t)NK * HID * HID];  // edge W^T [k][d][o] hi
__device__ uint16_t g_ewl[(size_t)NK * HID * HID];
__device__ uint16_t g_nwh[(size_t)NL * HID * HID];  // node W^T [l][d][o] hi (16384 stride)
__device__ uint16_t g_nwl[(size_t)NL * HID * HID];
__device__ float    g_ebsum[HID];

// ------------------------------- helpers -------------------------------
__device__ __forceinline__ void splitf(float a, uint16_t &h, uint16_t &l) {
    __nv_bfloat16 bh = __float2bfloat16(a);
    float res = a - __bfloat162float(bh);
    __nv_bfloat16 bl = __float2bfloat16(res);
    h = __bfloat16_as_ushort(bh);
    l = __bfloat16_as_ushort(bl);
}
__device__ __forceinline__ uint32_t packu(uint16_t a, uint16_t b) {
    return (uint32_t)a | ((uint32_t)b << 16);
}
__device__ __forceinline__ uint32_t cvta_s(const void* p) {
    return (uint32_t)__cvta_generic_to_shared(p);
}
__device__ __forceinline__ void ldsm_x4(uint32_t* r, uint32_t addr) {
    asm volatile("ldmatrix.sync.aligned.m8n8.x4.shared.b16 {%0,%1,%2,%3}, [%4];"
                 : "=r"(r[0]), "=r"(r[1]), "=r"(r[2]), "=r"(r[3]) : "r"(addr));
}
__device__ __forceinline__ void ldsm_x4_t(uint32_t* r, uint32_t addr) {
    asm volatile("ldmatrix.sync.aligned.m8n8.x4.trans.shared.b16 {%0,%1,%2,%3}, [%4];"
                 : "=r"(r[0]), "=r"(r[1]), "=r"(r[2]), "=r"(r[3]) : "r"(addr));
}
__device__ __forceinline__ void mma_bf16(float* c, const uint32_t* a, const uint32_t* b) {
    asm volatile("mma.sync.aligned.m16n8k16.row.col.f32.bf16.bf16.f32 "
                 "{%0,%1,%2,%3}, {%4,%5,%6,%7}, {%8,%9}, {%0,%1,%2,%3};"
                 : "+f"(c[0]), "+f"(c[1]), "+f"(c[2]), "+f"(c[3])
                 : "r"(a[0]), "r"(a[1]), "r"(a[2]), "r"(a[3]), "r"(b[0]), "r"(b[1]));
}
__device__ __forceinline__ void cp16(uint32_t dst, const void* src) {
    asm volatile("cp.async.cg.shared.global [%0], [%1], 16;" :: "r"(dst), "l"(src));
}
#define CP_COMMIT() asm volatile("cp.async.commit_group;")
#define CP_WAIT(n)  asm volatile("cp.async.wait_group %0;" :: "n"(n))

// ---------------------------------------------------------------------------------------
// prep: W [O=128][D] (optionally batched) -> transposed split planes [batch][d][o]
// ---------------------------------------------------------------------------------------
__global__ void prep_wt(const float* __restrict__ src, uint16_t* __restrict__ hi,
                        uint16_t* __restrict__ lo, int D)
{
    const int idx = blockIdx.x * 256 + threadIdx.x;     // over 128*D
    const int batch = blockIdx.y;
    const float* s = src + (size_t)batch * 128 * D;
    const int o = idx / D, d = idx % D;
    uint16_t h, l;
    splitf(s[idx], h, l);
    const size_t dst = (size_t)batch * D * 128 + (size_t)d * 128 + o;
    hi[dst] = h; lo[dst] = l;
}

__global__ void prep_feat(const float* __restrict__ f, uint16_t* __restrict__ hi,
                          uint16_t* __restrict__ lo)
{
    const int idx = blockIdx.x * 256 + threadIdx.x;     // MM*IND
    uint16_t h, l;
    splitf(f[idx], h, l);
    hi[idx] = h; lo[idx] = l;
}

__global__ void prep_ebsum(const float* __restrict__ eb, float* __restrict__ ebsum)
{
    const int h = threadIdx.x;
    ebsum[h] = eb[h] + eb[HID + h] + eb[2*HID + h] + eb[3*HID + h];
}

// ---------------------------------------------------------------------------------------
// Node linear (bf16x3 mma): Y = X @ W^T + b, X via split planes, W^T planes [d][o].
// Block: 128 rows x 128 cols, 8 warps x 16 rows. X tile + W fully smem-resident.
// ---------------------------------------------------------------------------------------
__global__ __launch_bounds__(256, 1) void lin_mma(
    const uint16_t* __restrict__ xhi, const uint16_t* __restrict__ xlo,
    const uint16_t* __restrict__ wh, const uint16_t* __restrict__ wl,
    const float* __restrict__ bias, float* __restrict__ Y,
    uint16_t* __restrict__ Yhi, uint16_t* __restrict__ Ylo, int D)
{
    extern __shared__ __align__(16) uint16_t lsm[];
    const uint32_t aX  = cvta_s(lsm);                    // 128 x EP (hi)
    const uint32_t pX  = 128 * EPB;                      // plane offset bytes
    const uint32_t aW  = aX + 2 * 128 * EPB;             // 128 x EP (hi)
    const uint32_t pW  = 128 * EPB;

    const int m0 = blockIdx.x * 128;
    const int tid = threadIdx.x, warp = tid >> 5, lane = tid & 31;
    const int rT = tid >> 4, cT = tid & 15;
    const uint32_t lds_off = (lane & 15) * EPB + ((lane >> 4) << 4);

    // stage X planes (rows 128 x D) and W planes (rows D x 128)
    const int dch = D >> 3;                              // 16B chunks per X row
    #pragma unroll
    for (int q = 0; q < 8; q++) {
        const int row = q * 16 + rT;
        if (cT < dch) {
            const size_t gi = (size_t)(m0 + row) * D + cT * 8;
            cp16(aX + row * EPB + cT * 16, xhi + gi);
            cp16(aX + pX + row * EPB + cT * 16, xlo + gi);
        }
    }
    for (int q = 0; q < (D >> 4); q++) {
        const int row = q * 16 + rT;
        const size_t gi = (size_t)row * 128 + cT * 8;
        cp16(aW + row * EPB + cT * 16, wh + gi);
        cp16(aW + pW + row * EPB + cT * 16, wl + gi);
    }
    CP_COMMIT(); CP_WAIT(0); __syncthreads();

    float macc[16][4];
    #pragma unroll
    for (int j = 0; j < 16; j++)
        #pragma unroll
        for (int t = 0; t < 4; t++) macc[j][t] = 0.f;

    for (int dc = 0; dc < (D >> 4); dc++) {
        uint32_t ah[4], al[4];
        const uint32_t axo = aX + (warp * 16 + (lane & 15)) * EPB + dc * 32 + ((lane >> 4) << 4);
        ldsm_x4(ah, axo);
        ldsm_x4(al, axo + pX);
        const uint32_t wb = aW + dc * 16 * EPB + lds_off;
        #pragma unroll
        for (int jj = 0; jj < 8; jj++) {
            uint32_t bh[4], bl[4];
            ldsm_x4_t(bh, wb + jj * 32);
            ldsm_x4_t(bl, wb + pW + jj * 32);
            #pragma unroll
            for (int tp = 0; tp < 2; tp++) {
                mma_bf16(macc[2*jj+tp], ah, &bh[2*tp]);
                mma_bf16(macc[2*jj+tp], ah, &bl[2*tp]);
                mma_bf16(macc[2*jj+tp], al, &bh[2*tp]);
            }
        }
    }

    // epilogue: +bias, write fp32 + split planes
    const int r0 = m0 + warp * 16 + (lane >> 2);
    #pragma unroll
    for (int j = 0; j < 16; j++) {
        const int col = j * 8 + (lane & 3) * 2;
        const float2 bb = *(const float2*)&bias[col];
        const float v0 = macc[j][0] + bb.x, v1 = macc[j][1] + bb.y;
        const float v2 = macc[j][2] + bb.x, v3 = macc[j][3] + bb.y;
        const size_t o0 = (size_t)r0 * HID + col;
        const size_t o1 = o0 + 8 * HID;
        *(float2*)&Y[o0] = make_float2(v0, v1);
        *(float2*)&Y[o1] = make_float2(v2, v3);
        uint16_t h0,l0,h1,l1;
        splitf(v0,h0,l0); splitf(v1,h1,l1);
        ((uint32_t*)Yhi)[o0 >> 1] = packu(h0,h1);
        ((uint32_t*)Ylo)[o0 >> 1] = packu(l0,l1);
        splitf(v2,h0,l0); splitf(v3,h1,l1);
        ((uint32_t*)Yhi)[o1 >> 1] = packu(h0,h1);
        ((uint32_t*)Ylo)[o1 >> 1] = packu(l0,l1);
    }
}

// ---------------------------------------------------------------------------------------
// Fused message passing + LN + ReLU.
// Grid (2, BB): block = 128 n-rows of one b, 8 warps x 16 rows x 128 cols.
// smem: full y tile (256 x 128, split planes) + W[k] region (prefetched during GEMM1).
// GEMM1: neigh_k (regs) = adj @ y  (adj A-frags direct from gmem; zero syncs)
// GEMM2: macc += neigh_k @ Wk^T
// Epilogue: v = y + macc + ebsum; x = relu(LN(v)); write fp32 + split planes.
// ---------------------------------------------------------------------------------------
__global__ __launch_bounds__(256, 1) void fused_mp(
    const float* __restrict__ adj, const uint16_t* __restrict__ yhi,
    const uint16_t* __restrict__ ylo, const uint16_t* __restrict__ wThi,
    const uint16_t* __restrict__ wTlo, const float* __restrict__ y,
    const float* __restrict__ ebsum, const float* __restrict__ lng,
    const float* __restrict__ lnb, float* __restrict__ xout,
    uint16_t* __restrict__ xhi, uint16_t* __restrict__ xlo)
{
    extern __shared__ __align__(16) uint16_t dsm[];
    const uint32_t aY = cvta_s(dsm);                     // 256 x EP (hi)
    const uint32_t pY = 256 * EPB;                       // lo plane offset (bytes)
    const uint32_t aW = aY + 2 * 256 * EPB;              // 128 x EP (hi)
    const uint32_t pW = 128 * EPB;

    const int b = blockIdx.y;
    const int n0 = blockIdx.x * 128;
    const int tid = threadIdx.x, warp = tid >> 5, lane = tid & 31;
    const int wrow = n0 + warp * 16;
    const int rT = tid >> 4, cT = tid & 15;
    const int ar = lane >> 2, ac = (lane & 3) * 2;
    const uint32_t lds_off = (lane & 15) * EPB + ((lane >> 4) << 4);

    // ---- stage full y tile (group 0) ----
    #pragma unroll
    for (int q = 0; q < 16; q++) {
        const int row = q * 16 + rT;
        const size_t gi = ((size_t)b * NN + row) * HID + cT * 8;
        cp16(aY + row * EPB + cT * 16, yhi + gi);
        cp16(aY + pY + row * EPB + cT * 16, ylo + gi);
    }
    CP_COMMIT();
    // ---- stage W[0] (group 1) ----
    #pragma unroll
    for (int q = 0; q < 8; q++) {
        const int row = q * 16 + rT;
        const size_t gi = (size_t)row * 128 + cT * 8;
        cp16(aW + row * EPB + cT * 16, wThi + gi);
        cp16(aW + pW + row * EPB + cT * 16, wTlo + gi);
    }
    CP_COMMIT();
    CP_WAIT(1); __syncthreads();   // y resident

    float macc[16][4];
    #pragma unroll
    for (int j = 0; j < 16; j++)
        #pragma unroll
        for (int t = 0; t < 4; t++) macc[j][t] = 0.f;

    for (int k = 0; k < NK; k++) {
        // -------- GEMM1: nacc = adj_k @ y (no syncs; y resident) --------
        float nacc[16][4];
        #pragma unroll
        for (int j = 0; j < 16; j++)
            #pragma unroll
            for (int t = 0; t < 4; t++) nacc[j][t] = 0.f;

        const float* Ap = adj + (((size_t)(b * NK + k) * NN + wrow) * NN);
        float2 adjP[2][4];
        adjP[0][0] = *(const float2*)(Ap + (size_t)ar * NN + ac);
        adjP[0][1] = *(const float2*)(Ap + (size_t)(ar+8) * NN + ac);
        adjP[0][2] = *(const float2*)(Ap + (size_t)ar * NN + ac + 8);
        adjP[0][3] = *(const float2*)(Ap + (size_t)(ar+8) * NN + ac + 8);

        #pragma unroll
        for (int mc = 0; mc < 16; mc++) {
            if (mc < 15) {
                const float* An = Ap + (mc + 1) * 16;
                adjP[(mc+1)&1][0] = *(const float2*)(An + (size_t)ar * NN + ac);
                adjP[(mc+1)&1][1] = *(const float2*)(An + (size_t)(ar+8) * NN + ac);
                adjP[(mc+1)&1][2] = *(const float2*)(An + (size_t)ar * NN + ac + 8);
                adjP[(mc+1)&1][3] = *(const float2*)(An + (size_t)(ar+8) * NN + ac + 8);
            }
            uint32_t ah[4], al[4];
            #pragma unroll
            for (int q = 0; q < 4; q++) {
                uint16_t h0,l0,h1,l1;
                splitf(adjP[mc&1][q].x, h0, l0);
                splitf(adjP[mc&1][q].y, h1, l1);
                ah[q] = packu(h0,h1); al[q] = packu(l0,l1);
            }
            const uint32_t yb = aY + mc * 16 * EPB + lds_off;
            #pragma unroll
            for (int jj = 0; jj < 8; jj++) {
                uint32_t bh[4], bl[4];
                ldsm_x4_t(bh, yb + jj * 32);
                ldsm_x4_t(bl, yb + pY + jj * 32);
                #pragma unroll
                for (int tp = 0; tp < 2; tp++) {
                    mma_bf16(nacc[2*jj+tp], ah, &bh[2*tp]);
                    mma_bf16(nacc[2*jj+tp], ah, &bl[2*tp]);
                    mma_bf16(nacc[2*jj+tp], al, &bh[2*tp]);
                }
            }
        }

        CP_WAIT(0); __syncthreads();   // W[k] resident

        // -------- GEMM2: macc += nacc @ W_k^T --------
        #pragma unroll
        for (int hc = 0; hc < 8; hc++) {
            uint32_t ah[4], al[4];
            {
                uint16_t h0,l0,h1,l1;
                splitf(nacc[2*hc][0],h0,l0);   splitf(nacc[2*hc][1],h1,l1);
                ah[0]=packu(h0,h1); al[0]=packu(l0,l1);
                splitf(nacc[2*hc][2],h0,l0);   splitf(nacc[2*hc][3],h1,l1);
                ah[1]=packu(h0,h1); al[1]=packu(l0,l1);
                splitf(nacc[2*hc+1][0],h0,l0); splitf(nacc[2*hc+1][1],h1,l1);
                ah[2]=packu(h0,h1); al[2]=packu(l0,l1);
                splitf(nacc[2*hc+1][2],h0,l0); splitf(nacc[2*hc+1][3],h1,l1);
                ah[3]=packu(h0,h1); al[3]=packu(l0,l1);
            }
            const uint32_t wb = aW + hc * 16 * EPB + lds_off;
            #pragma unroll
            for (int jj = 0; jj < 8; jj++) {
                uint32_t bh[4], bl[4];
                ldsm_x4_t(bh, wb + jj * 32);
                ldsm_x4_t(bl, wb + pW + jj * 32);
                #pragma unroll
                for (int tp = 0; tp < 2; tp++) {
                    mma_bf16(macc[2*jj+tp], ah, &bh[2*tp]);
                    mma_bf16(macc[2*jj+tp], ah, &bl[2*tp]);
                    mma_bf16(macc[2*jj+tp], al, &bh[2*tp]);
                }
            }
        }
        __syncthreads();               // all warps done reading W[k]
        if (k < NK - 1) {
            #pragma unroll
            for (int q = 0; q < 8; q++) {
                const int row = q * 16 + rT;
                const size_t gi = ((size_t)(k + 1) << 14) + (size_t)row * 128 + cT * 8;
                cp16(aW + row * EPB + cT * 16, wThi + gi);
                cp16(aW + pW + row * EPB + cT * 16, wTlo + gi);
            }
            CP_COMMIT();
        }
    }

    // -------- epilogue: residual + ebsum + LN + ReLU + split --------
    const int r0 = wrow + (lane >> 2);
    const int r1 = r0 + 8;
    // v = y + macc + ebsum, accumulate sums
    float s0 = 0.f, q0 = 0.f, s1 = 0.f, q1 = 0.f;
    #pragma unroll
    for (int j = 0; j < 16; j++) {
        const int col = j * 8 + (lane & 3) * 2;
        const float2 e = *(const float2*)&ebsum[col];
        const float2 y0 = *(const float2*)&y[((size_t)b * NN + r0) * HID + col];
        const float2 y1 = *(const float2*)&y[((size_t)b * NN + r1) * HID + col];
        macc[j][0] += y0.x + e.x;  macc[j][1] += y0.y + e.y;
        macc[j][2] += y1.x + e.x;  macc[j][3] += y1.y + e.y;
        s0 += macc[j][0] + macc[j][1];
        q0 += macc[j][0]*macc[j][0] + macc[j][1]*macc[j][1];
        s1 += macc[j][2] + macc[j][3];
        q1 += macc[j][2]*macc[j][2] + macc[j][3]*macc[j][3];
    }
    #pragma unroll
    for (int d = 1; d <= 2; d <<= 1) {
        s0 += __shfl_xor_sync(0xffffffffu, s0, d);
        q0 += __shfl_xor_sync(0xffffffffu, q0, d);
        s1 += __shfl_xor_sync(0xffffffffu, s1, d);
        q1 += __shfl_xor_sync(0xffffffffu, q1, d);
    }
    const float mu0 = s0 * (1.f/HID), mu1 = s1 * (1.f/HID);
    const float ri0 = rsqrtf(q0 * (1.f/HID) - mu0*mu0 + LN_EPS);
    const float ri1 = rsqrtf(q1 * (1.f/HID) - mu1*mu1 + LN_EPS);

    #pragma unroll
    for (int j = 0; j < 16; j++) {
        const int col = j * 8 + (lane & 3) * 2;
        const float2 gg = *(const float2*)&lng[col];
        const float2 bb = *(const float2*)&lnb[col];
        const float o0 = fmaxf((macc[j][0]-mu0)*ri0*gg.x + bb.x, 0.f);
        const float o1 = fmaxf((macc[j][1]-mu0)*ri0*gg.y + bb.y, 0.f);
        const float o2 = fmaxf((macc[j][2]-mu1)*ri1*gg.x + bb.x, 0.f);
        const float o3 = fmaxf((macc[j][3]-mu1)*ri1*gg.y + bb.y, 0.f);
        const size_t w0 = ((size_t)b * NN + r0) * HID + col;
        const size_t w1 = ((size_t)b * NN + r1) * HID + col;
        *(float2*)&xout[w0] = make_float2(o0, o1);
        *(float2*)&xout[w1] = make_float2(o2, o3);
        uint16_t h0,l0,h1,l1;
        splitf(o0,h0,l0); splitf(o1,h1,l1);
        ((uint32_t*)xhi)[w0 >> 1] = packu(h0,h1);
        ((uint32_t*)xlo)[w0 >> 1] = packu(l0,l1);
        splitf(o2,h0,l0); splitf(o3,h1,l1);
        ((uint32_t*)xhi)[w1 >> 1] = packu(h0,h1);
        ((uint32_t*)xlo)[w1 >> 1] = packu(l0,l1);
    }
}

// ---------------------------------------------------------------------------------------
__global__ void readout_kernel(const float* __restrict__ x, const float* __restrict__ oW,
                               const float* __restrict__ ob, float* __restrict__ out)
{
    const int b = blockIdx.x;
    const int h = threadIdx.x;
    float s = 0.0f;
    const float* xp = x + (size_t)b * NN * HID + h;
    #pragma unroll 8
    for (int n = 0; n < NN; n++) s += xp[(size_t)n * HID];
    __shared__ float repr[HID];
    repr[h] = s;
    __syncthreads();
    if (h < NOUT) {
        float acc = ob[h];
        #pragma unroll 8
        for (int d = 0; d < HID; d++) acc += repr[d] * oW[h * HID + d];
        out[b * NOUT + h] = acc;
    }
}

// ---------------------------------------------------------------------------------------
extern "C" void kernel_launch(void* const* d_in, const int* in_sizes, int n_in,
                              void* d_out, int out_size)
{
    const float* feat = (const float*)d_in[0];
    const float* adj  = (const float*)d_in[1];
    const float* nW[3] = {(const float*)d_in[2], (const float*)d_in[4], (const float*)d_in[6]};
    const float* nb[3] = {(const float*)d_in[3], (const float*)d_in[5], (const float*)d_in[7]};
    const float* eW  = (const float*)d_in[8];
    const float* ebp = (const float*)d_in[9];
    const float* lng = (const float*)d_in[10];
    const float* lnb = (const float*)d_in[11];
    const float* oW  = (const float*)d_in[12];
    const float* ob  = (const float*)d_in[13];

    float *y, *xb, *ebs;
    uint16_t *yhi, *ylo, *xhi, *xlo, *ewh, *ewl, *nwh, *nwl;
    cudaGetSymbolAddress((void**)&y,   g_y);
    cudaGetSymbolAddress((void**)&yhi, g_yhi);
    cudaGetSymbolAddress((void**)&ylo, g_ylo);
    cudaGetSymbolAddress((void**)&xb,  g_x);
    cudaGetSymbolAddress((void**)&xhi, g_xhi);
    cudaGetSymbolAddress((void**)&xlo, g_xlo);
    cudaGetSymbolAddress((void**)&ewh, g_ewh);
    cudaGetSymbolAddress((void**)&ewl, g_ewl);
    cudaGetSymbolAddress((void**)&nwh, g_nwh);
    cudaGetSymbolAddress((void**)&nwl, g_nwl);
    cudaGetSymbolAddress((void**)&ebs, g_ebsum);

    const int FUSED_SMEM = (2 * 256 + 2 * 128) * EPB;   // 208896 B
    const int LIN_SMEM   = 4 * 128 * EPB;               // 139264 B
    cudaFuncSetAttribute(fused_mp, cudaFuncAttributeMaxDynamicSharedMemorySize, FUSED_SMEM);
    cudaFuncSetAttribute(lin_mma,  cudaFuncAttributeMaxDynamicSharedMemorySize, LIN_SMEM);

    // weight prep: node (D=64, 128, 128) + edge (4 x D=128)
    prep_wt<<<dim3(128*IND/256, 1), 256>>>(nW[0], nwh, nwl, IND);
    prep_wt<<<dim3(128*HID/256, 1), 256>>>(nW[1], nwh + 16384, nwl + 16384, HID);
    prep_wt<<<dim3(128*HID/256, 1), 256>>>(nW[2], nwh + 32768, nwl + 32768, HID);
    prep_wt<<<dim3(128*HID/256, NK), 256>>>(eW, ewh, ewl, HID);
    prep_feat<<<MM*IND/256, 256>>>(feat, xhi, xlo);
    prep_ebsum<<<1, HID>>>(ebp, ebs);

    int D = IND;
    for (int l = 0; l < NL; l++) {
        lin_mma<<<MM/128, 256, LIN_SMEM>>>(xhi, xlo, nwh + l*16384, nwl + l*16384,
                                           nb[l], y, yhi, ylo, D);
        fused_mp<<<dim3(2, BB), 256, FUSED_SMEM>>>(adj, yhi, ylo, ewh, ewl, y, ebs,
                                                   lng + l*HID, lnb + l*HID, xb, xhi, xlo);
        D = HID;
    }
    readout_kernel<<<BB, HID>>>(xb, oW, ob, (float*)d_out);
}